// round 6
// baseline (speedup 1.0000x reference)
#include <cuda_runtime.h>
#include <cstdint>

#define VOCAB 50000
#define EMBD  300
#define HID   64
#define G4    256      // 4*H
#define D2    128      // 2*H
#define BATCH 128
#define TBODY 512
#define TPUN  256

// ---------------- scratch (static device arrays: allocation-free) ----------------
__device__ float    g_tbl[(size_t)4 * VOCAB * G4];          // 204.8 MB gate tables
__device__ float    g_bodyM[(size_t)BATCH * TBODY * D2];    // 33.5 MB
__device__ float    g_punM[(size_t)BATCH * TPUN * D2];      // 16.8 MB
__device__ float    g_rowmax[BATCH * TBODY];
__device__ unsigned g_colmax[BATCH * TPUN];                 // ordered-int encoded

// ---------------- helpers ----------------
__device__ __forceinline__ unsigned enc_f(float f) {
    unsigned u = __float_as_uint(f);
    return (u & 0x80000000u) ? ~u : (u | 0x80000000u);
}
__device__ __forceinline__ float dec_f(unsigned u) {
    return __uint_as_float((u & 0x80000000u) ? (u ^ 0x80000000u) : ~u);
}
// packed fp32x2 FMA (sm_100+): 2 FMA per lane per issue
__device__ __forceinline__ unsigned long long ffma2(unsigned long long a,
                                                    unsigned long long b,
                                                    unsigned long long c) {
    unsigned long long d;
    asm("fma.rn.f32x2 %0, %1, %2, %3;" : "=l"(d) : "l"(a), "l"(b), "l"(c));
    return d;
}
__device__ __forceinline__ unsigned long long pk2(float x) {
    unsigned long long r;
    asm("mov.b64 %0, {%1, %1};" : "=l"(r) : "f"(x));
    return r;
}
__device__ __forceinline__ float2 up2(unsigned long long p) {
    float2 r;
    asm("mov.b64 {%0, %1}, %2;" : "=f"(r.x), "=f"(r.y) : "l"(p));
    return r;
}

// ---------------- kernel 0: init colmax ----------------
__global__ void init_colmax_kernel() {
    int i = blockIdx.x * blockDim.x + threadIdx.x;
    if (i < BATCH * TPUN) g_colmax[i] = 0u;   // below enc of any finite float
}

// ---------------- kernel 1: gate-table GEMM  tbl[v,g] = emb[v,:]·Wih[g,:] + b[g] ----
// M=50000, N=256 per seg, K=300. Tile 128x128, BK=20 (300=15*20), 256 thr, 8x8 micro, FFMA2.
#define BM 128
#define BN 128
#define BK 20
__global__ void __launch_bounds__(256) gemm_tbl_kernel(
    const float* __restrict__ emb,
    const float* __restrict__ W0, const float* __restrict__ W1,
    const float* __restrict__ W2, const float* __restrict__ W3,
    const float* __restrict__ B0, const float* __restrict__ B1,
    const float* __restrict__ B2, const float* __restrict__ B3)
{
    int seg = blockIdx.z;
    const float* W    = (seg == 0) ? W0 : (seg == 1) ? W1 : (seg == 2) ? W2 : W3;
    const float* bias = (seg == 0) ? B0 : (seg == 1) ? B1 : (seg == 2) ? B2 : B3;
    float* out = g_tbl + (size_t)seg * VOCAB * G4;

    int m0 = blockIdx.x * BM;
    int n0 = blockIdx.y * BN;

    __shared__ __align__(16) float As[BK][BM + 4];   // row stride 132 floats (16B-mult)
    __shared__ __align__(16) float Bs[BK][BN + 4];

    int tid = threadIdx.x;
    int tx = tid & 15, ty = tid >> 4;

    unsigned long long acc[8][4];
#pragma unroll
    for (int i = 0; i < 8; i++)
#pragma unroll
        for (int j = 0; j < 4; j++) acc[i][j] = 0ull;

    for (int k0 = 0; k0 < EMBD; k0 += BK) {
#pragma unroll
        for (int it = 0; it < 10; it++) {
            int l = tid + 256 * it;          // l < 2560
            int r = l / BK, kk = l - r * BK;
            int gr = m0 + r;
            As[kk][r] = (gr < VOCAB) ? emb[(size_t)gr * EMBD + k0 + kk] : 0.f;
        }
#pragma unroll
        for (int it = 0; it < 10; it++) {
            int l = tid + 256 * it;
            int r = l / BK, kk = l - r * BK;
            Bs[kk][r] = W[(size_t)(n0 + r) * EMBD + k0 + kk];
        }
        __syncthreads();
#pragma unroll
        for (int kk = 0; kk < BK; kk++) {
            float4 a0 = *(const float4*)&As[kk][ty * 4];
            float4 a1 = *(const float4*)&As[kk][64 + ty * 4];
            ulonglong2 b0 = *(const ulonglong2*)&Bs[kk][tx * 4];
            ulonglong2 b1 = *(const ulonglong2*)&Bs[kk][64 + tx * 4];
            unsigned long long ap[8];
            ap[0] = pk2(a0.x); ap[1] = pk2(a0.y); ap[2] = pk2(a0.z); ap[3] = pk2(a0.w);
            ap[4] = pk2(a1.x); ap[5] = pk2(a1.y); ap[6] = pk2(a1.z); ap[7] = pk2(a1.w);
#pragma unroll
            for (int i = 0; i < 8; i++) {
                acc[i][0] = ffma2(ap[i], b0.x, acc[i][0]);
                acc[i][1] = ffma2(ap[i], b0.y, acc[i][1]);
                acc[i][2] = ffma2(ap[i], b1.x, acc[i][2]);
                acc[i][3] = ffma2(ap[i], b1.y, acc[i][3]);
            }
        }
        __syncthreads();
    }

    float4 bs0 = *(const float4*)&bias[n0 + tx * 4];
    float4 bs1 = *(const float4*)&bias[n0 + 64 + tx * 4];
#pragma unroll
    for (int i = 0; i < 8; i++) {
        int r = m0 + ty * 4 + (i & 3) + (i >> 2) * 64;
        if (r < VOCAB) {
            float2 v0 = up2(acc[i][0]), v1 = up2(acc[i][1]);
            float2 v2 = up2(acc[i][2]), v3 = up2(acc[i][3]);
            float4 o0 = make_float4(v0.x + bs0.x, v0.y + bs0.y, v1.x + bs0.z, v1.y + bs0.w);
            float4 o1 = make_float4(v2.x + bs1.x, v2.y + bs1.y, v3.x + bs1.z, v3.y + bs1.w);
            *(float4*)&out[(size_t)r * G4 + n0 + tx * 4] = o0;
            *(float4*)&out[(size_t)r * G4 + n0 + 64 + tx * 4] = o1;
        }
    }
}

// ---------------- kernel 2: LSTM (4 runs x 128 batches = 512 blocks, 256 thr) ----------------
__global__ void __launch_bounds__(256) lstm_kernel(
    const int* __restrict__ body_idx, const int* __restrict__ pun_idx,
    const float* __restrict__ Whh0, const float* __restrict__ Whh1,
    const float* __restrict__ Whh2, const float* __restrict__ Whh3)
{
    int blk = blockIdx.x;
    int seg = blk >> 7;
    int b   = blk & 127;
    bool isBody = (seg < 2);
    bool isFwd  = ((seg & 1) == 0);
    int T = isBody ? TBODY : TPUN;
    const int* idx = isBody ? (body_idx + b * TBODY) : (pun_idx + b * TPUN);
    const float* Whh = (seg == 0) ? Whh0 : (seg == 1) ? Whh1 : (seg == 2) ? Whh2 : Whh3;
    const float* tbl = g_tbl + (size_t)seg * VOCAB * G4;
    float* out = isBody ? (g_bodyM + (size_t)b * TBODY * D2)
                        : (g_punM  + (size_t)b * TPUN  * D2);
    int off = isFwd ? 0 : HID;

    __shared__ int idx_s[TBODY];
    __shared__ __align__(16) float hs[HID];
    __shared__ float gs[G4];
    __shared__ int len_s;

    int tid = threadIdx.x;
    int g = tid;

    if (tid == 0) len_s = 0;
    if (tid < HID) hs[tid] = 0.f;
    __syncthreads();

    int cnt = 0;
    for (int t = tid; t < T; t += 256) {
        int v = idx[t];
        idx_s[t] = v;
        cnt += (v != 0);
    }
#pragma unroll
    for (int o = 16; o; o >>= 1) cnt += __shfl_xor_sync(0xFFFFFFFFu, cnt, o);
    if ((tid & 31) == 0) atomicAdd(&len_s, cnt);
    __syncthreads();
    int len = len_s;

    float w[HID];
#pragma unroll
    for (int j = 0; j < HID; j++) w[j] = Whh[(size_t)g * HID + j];

    float c = 0.f;
    float x1 = 0.f, x2 = 0.f;
    if (len > 0) x1 = tbl[(size_t)idx_s[isFwd ? 0 : (len - 1)] * G4 + g];
    if (len > 1) x2 = tbl[(size_t)idx_s[isFwd ? 1 : (len - 2)] * G4 + g];

    const float4* hv4 = (const float4*)hs;
    for (int t = 0; t < len; t++) {
        float xs = x1;
        x1 = x2;
        if (t + 2 < len) {
            int p2 = isFwd ? (t + 2) : (len - 3 - t);
            x2 = tbl[(size_t)idx_s[p2] * G4 + g];
        }
        // 4-chain dot product: dependency depth 16 instead of 64
        float a0 = xs, a1 = 0.f, a2 = 0.f, a3 = 0.f;
#pragma unroll
        for (int jj = 0; jj < 16; jj++) {
            float4 h4 = hv4[jj];
            a0 += w[4 * jj + 0] * h4.x;
            a1 += w[4 * jj + 1] * h4.y;
            a2 += w[4 * jj + 2] * h4.z;
            a3 += w[4 * jj + 3] * h4.w;
        }
        float pre = (a0 + a1) + (a2 + a3);
        // gate order i,f,g,o ; g-gate tanh, others sigmoid (accurate paths)
        float act = (g >= 128 && g < 192) ? tanhf(pre)
                                          : 1.f / (1.f + __expf(-pre));
        gs[g] = act;
        __syncthreads();
        if (g < HID) {
            float cn = gs[HID + g] * c + gs[g] * gs[128 + g];
            c = cn;
            float h = gs[192 + g] * tanhf(cn);
            hs[g] = h;
            int pos = isFwd ? t : (len - 1 - t);
            out[(size_t)pos * D2 + off + g] = h;
        }
        __syncthreads();
    }
    for (int l = tid; l < (T - len) * HID; l += 256) {
        int tpos = len + l / HID;
        int j = l - (l / HID) * HID;
        out[(size_t)tpos * D2 + off + j] = 0.f;
    }
}

// ---------------- kernel 3: alignment maxes ----------------
// grid = 128 batches * 4 t-chunks of 128. 256 thr (16x16 micro grid).
// Resident smem: body chunk [128 d][128 t] (xw3) + pun [128 d][256 p], transposed; FFMA2 micro.
#define BT_STRIDE 132   // 128 + 4 pad (16B multiple)
#define PT_STRIDE 260   // 256 + 4 pad
#define ALIGN_DYN_BYTES ((128 * BT_STRIDE + 128 * PT_STRIDE) * 4)

__global__ void __launch_bounds__(256) align_kernel(const float* __restrict__ w_u)
{
    int b  = blockIdx.x >> 2;
    int tc = blockIdx.x & 3;
    int t0 = tc * 128;
    const float* bodyM = g_bodyM + (size_t)b * TBODY * D2;
    const float* punM  = g_punM  + (size_t)b * TPUN  * D2;

    extern __shared__ __align__(16) float dyn[];
    float* Bt = dyn;                        // Bt[d][t] : d*BT_STRIDE + t
    float* Pt = dyn + 128 * BT_STRIDE;      // Pt[d][p] : d*PT_STRIDE + p

    __shared__ float w1s[D2], w2s[D2];
    __shared__ float a1s[128], a2s[TPUN];
    __shared__ unsigned rms[128];
    __shared__ unsigned cms[TPUN];

    int tid = threadIdx.x;
    int tx = tid & 15, ty = tid >> 4;
    int warp = tid >> 5, lane = tid & 31;

    if (tid < D2) { w1s[tid] = w_u[tid]; w2s[tid] = w_u[D2 + tid]; }
    if (tid < 128) rms[tid] = 0u;
    cms[tid] = 0u;
    __syncthreads();
    float w3v = (tid < D2) ? w_u[2 * D2 + tid] : 0.f;   // unused; w3 applied below via w_u

    // a1 for local 128 t rows; a2 for all 256 p rows (warp-per-row)
    for (int r = warp; r < 128; r += 8) {
        const float* row = bodyM + (size_t)(t0 + r) * D2;
        float s = 0.f;
        for (int d = lane; d < D2; d += 32) s += row[d] * w1s[d];
#pragma unroll
        for (int o = 16; o; o >>= 1) s += __shfl_xor_sync(0xFFFFFFFFu, s, o);
        if (lane == 0) a1s[r] = s;
    }
    for (int r = warp; r < TPUN; r += 8) {
        const float* row = punM + (size_t)r * D2;
        float s = 0.f;
        for (int d = lane; d < D2; d += 32) s += row[d] * w2s[d];
#pragma unroll
        for (int o = 16; o; o >>= 1) s += __shfl_xor_sync(0xFFFFFFFFu, s, o);
        if (lane == 0) a2s[r] = s;
    }

    // transposed tile loads (coalesced global reads)
#pragma unroll 4
    for (int l = tid; l < 128 * 128; l += 256) {
        int r = l >> 7, dd = l & 127;
        Bt[dd * BT_STRIDE + r] = bodyM[(size_t)(t0 + r) * D2 + dd] * w_u[2 * D2 + dd];
    }
#pragma unroll 4
    for (int l = tid; l < 256 * 128; l += 256) {
        int p = l >> 7, dd = l & 127;
        Pt[dd * PT_STRIDE + p] = punM[(size_t)p * D2 + dd];
    }
    __syncthreads();
    (void)w3v;

    float rmax[8];
#pragma unroll
    for (int i = 0; i < 8; i++) rmax[i] = -1e30f;

    for (int ph = 0; ph < 2; ph++) {            // p in [ph*128, ph*128+128)
        unsigned long long acc[8][4];
#pragma unroll
        for (int i = 0; i < 8; i++)
#pragma unroll
            for (int j = 0; j < 4; j++) acc[i][j] = 0ull;

        int p0 = ph * 128 + tx * 4;
#pragma unroll 4
        for (int d = 0; d < D2; d++) {
            const float* bd0 = Bt + d * BT_STRIDE;
            const float* pd0 = Pt + d * PT_STRIDE;
            float4 a0 = *(const float4*)&bd0[ty * 4];
            float4 a1 = *(const float4*)&bd0[64 + ty * 4];
            ulonglong2 b0 = *(const ulonglong2*)&pd0[p0];
            ulonglong2 b1 = *(const ulonglong2*)&pd0[p0 + 64];
            unsigned long long ap[8];
            ap[0] = pk2(a0.x); ap[1] = pk2(a0.y); ap[2] = pk2(a0.z); ap[3] = pk2(a0.w);
            ap[4] = pk2(a1.x); ap[5] = pk2(a1.y); ap[6] = pk2(a1.z); ap[7] = pk2(a1.w);
#pragma unroll
            for (int i = 0; i < 8; i++) {
                acc[i][0] = ffma2(ap[i], b0.x, acc[i][0]);
                acc[i][1] = ffma2(ap[i], b0.y, acc[i][1]);
                acc[i][2] = ffma2(ap[i], b1.x, acc[i][2]);
                acc[i][3] = ffma2(ap[i], b1.y, acc[i][3]);
            }
        }
        // combine with a1/a2, track maxes
        float cmax[8];
#pragma unroll
        for (int j = 0; j < 8; j++) cmax[j] = -1e30f;
#pragma unroll
        for (int i = 0; i < 8; i++) {
            int trow = ty * 4 + (i & 3) + (i >> 2) * 64;
            float a1v = a1s[trow];
#pragma unroll
            for (int jp = 0; jp < 4; jp++) {
                float2 v = up2(acc[i][jp]);
                int c0 = p0 + (jp >> 1) * 64 + (jp & 1) * 2;
                float v0 = v.x + a1v + a2s[c0];
                float v1 = v.y + a1v + a2s[c0 + 1];
                rmax[i] = fmaxf(rmax[i], fmaxf(v0, v1));
                int jj = (jp >> 1) * 4 + (jp & 1) * 2;
                cmax[jj]     = fmaxf(cmax[jj], v0);
                cmax[jj + 1] = fmaxf(cmax[jj + 1], v1);
            }
        }
#pragma unroll
        for (int j = 0; j < 8; j++) {
            int col = ph * 128 + tx * 4 + (j >> 2) * 64 + (j & 3);
            atomicMax(&cms[col], enc_f(cmax[j]));
        }
    }
#pragma unroll
    for (int i = 0; i < 8; i++) {
        int trow = ty * 4 + (i & 3) + (i >> 2) * 64;
        atomicMax(&rms[trow], enc_f(rmax[i]));
    }
    __syncthreads();

    if (tid < 128) g_rowmax[b * TBODY + t0 + tid] = dec_f(rms[tid]);
    atomicMax(&g_colmax[b * TPUN + tid], cms[tid]);
}

// ---------------- kernel 4: softmaxes + weighted sums + final linear ----------------
__global__ void __launch_bounds__(256) final_kernel(
    const float* __restrict__ Wd, const float* __restrict__ bd,
    float* __restrict__ outp)
{
    int b = blockIdx.x;
    int tid = threadIdx.x;
    int lane = tid & 31, warp = tid >> 5;

    __shared__ float attb[TBODY];
    __shared__ float attp[TPUN];
    __shared__ float feat[G4];
    __shared__ float sred[8];

    // softmax over rowmax[512]
    float v0 = g_rowmax[b * TBODY + tid];
    float v1 = g_rowmax[b * TBODY + 256 + tid];
    float m = fmaxf(v0, v1);
#pragma unroll
    for (int o = 16; o; o >>= 1) m = fmaxf(m, __shfl_xor_sync(0xFFFFFFFFu, m, o));
    if (lane == 0) sred[warp] = m;
    __syncthreads();
    float M = sred[0];
#pragma unroll
    for (int w = 1; w < 8; w++) M = fmaxf(M, sred[w]);
    __syncthreads();
    float e0 = __expf(v0 - M), e1 = __expf(v1 - M);
    float ss = e0 + e1;
#pragma unroll
    for (int o = 16; o; o >>= 1) ss += __shfl_xor_sync(0xFFFFFFFFu, ss, o);
    if (lane == 0) sred[warp] = ss;
    __syncthreads();
    float S = 0.f;
#pragma unroll
    for (int w = 0; w < 8; w++) S += sred[w];
    __syncthreads();
    attb[tid] = e0 / S;
    attb[256 + tid] = e1 / S;

    // softmax over colmax[256]
    float u = dec_f(g_colmax[b * TPUN + tid]);
    float m2 = u;
#pragma unroll
    for (int o = 16; o; o >>= 1) m2 = fmaxf(m2, __shfl_xor_sync(0xFFFFFFFFu, m2, o));
    if (lane == 0) sred[warp] = m2;
    __syncthreads();
    float M2 = sred[0];
#pragma unroll
    for (int w = 1; w < 8; w++) M2 = fmaxf(M2, sred[w]);
    __syncthreads();
    float e2 = __expf(u - M2);
    float ss2 = e2;
#pragma unroll
    for (int o = 16; o; o >>= 1) ss2 += __shfl_xor_sync(0xFFFFFFFFu, ss2, o);
    if (lane == 0) sred[warp] = ss2;
    __syncthreads();
    float S2 = 0.f;
#pragma unroll
    for (int w = 0; w < 8; w++) S2 += sred[w];
    __syncthreads();
    attp[tid] = e2 / S2;
    __syncthreads();

    // weighted sums -> feat[256]
    if (tid < D2) {
        const float* bm = g_bodyM + (size_t)b * TBODY * D2 + tid;
        float s = 0.f;
#pragma unroll 8
        for (int t = 0; t < TBODY; t++) s += bm[(size_t)t * D2] * attb[t];
        feat[tid] = s;
    } else {
        int d = tid - D2;
        const float* pm = g_punM + (size_t)b * TPUN * D2 + d;
        float s = 0.f;
#pragma unroll 8
        for (int p = 0; p < TPUN; p++) s += pm[(size_t)p * D2] * attp[p];
        feat[D2 + d] = s;
    }
    __syncthreads();

    if (tid < 3) {
        float s = bd[tid];
        for (int k = 0; k < G4; k++) s += feat[k] * Wd[tid * G4 + k];
        outp[b * 3 + tid] = s;
    }
}

// ---------------- host launcher ----------------
extern "C" void kernel_launch(void* const* d_in, const int* in_sizes, int n_in,
                              void* d_out, int out_size)
{
    // Disambiguate input ordering: signature order has bWih_f (76800) at index 3,
    // dict-insertion order has w_u (384) at index 3.
    int base, iwu, iwd, ibd;
    if (in_sizes[3] == 76800) { base = 3; iwu = 15; iwd = 16; ibd = 17; }
    else                      { base = 6; iwu = 3;  iwd = 4;  ibd = 5;  }

    const int*   body_idx = (const int*)d_in[0];
    const int*   pun_idx  = (const int*)d_in[1];
    const float* emb      = (const float*)d_in[2];

    const float* Wih[4]; const float* Whh[4]; const float* bv[4];
    for (int s = 0; s < 4; s++) {
        Wih[s] = (const float*)d_in[base + 3 * s + 0];
        Whh[s] = (const float*)d_in[base + 3 * s + 1];
        bv[s]  = (const float*)d_in[base + 3 * s + 2];
    }
    const float* w_u = (const float*)d_in[iwu];
    const float* Wd  = (const float*)d_in[iwd];
    const float* bd  = (const float*)d_in[ibd];
    float* outp = (float*)d_out;

    // opt-in to large dynamic smem for align_kernel (idempotent, capture-safe)
    cudaFuncSetAttribute(align_kernel, cudaFuncAttributeMaxDynamicSharedMemorySize,
                         ALIGN_DYN_BYTES);

    init_colmax_kernel<<<(BATCH * TPUN + 255) / 256, 256>>>();

    dim3 gg((VOCAB + BM - 1) / BM, G4 / BN, 4);
    gemm_tbl_kernel<<<gg, 256>>>(emb, Wih[0], Wih[1], Wih[2], Wih[3],
                                 bv[0], bv[1], bv[2], bv[3]);

    lstm_kernel<<<512, 256>>>(body_idx, pun_idx, Whh[0], Whh[1], Whh[2], Whh[3]);

    align_kernel<<<512, 256, ALIGN_DYN_BYTES>>>(w_u);

    final_kernel<<<BATCH, 256>>>(Wd, bd, outp);
    (void)n_in; (void)out_size;
}

// round 7
// speedup vs baseline: 1.1679x; 1.1679x over previous
#include <cuda_runtime.h>
#include <cstdint>

#define VOCAB 50000
#define EMBD  300
#define HID   64
#define G4    256      // 4*H
#define D2    128      // 2*H
#define BATCH 128
#define TBODY 512
#define TPUN  256

// ---------------- scratch (static device arrays: allocation-free) ----------------
__device__ float    g_tbl[(size_t)4 * VOCAB * G4];          // 204.8 MB gate tables
__device__ float    g_bodyM[(size_t)BATCH * TBODY * D2];    // 33.5 MB
__device__ float    g_punM[(size_t)BATCH * TPUN * D2];      // 16.8 MB
__device__ unsigned g_rowmax[BATCH * TBODY];                // ordered-int encoded
__device__ unsigned g_colmax[BATCH * TPUN];                 // ordered-int encoded

// ---------------- helpers ----------------
__device__ __forceinline__ unsigned enc_f(float f) {
    unsigned u = __float_as_uint(f);
    return (u & 0x80000000u) ? ~u : (u | 0x80000000u);
}
__device__ __forceinline__ float dec_f(unsigned u) {
    return __uint_as_float((u & 0x80000000u) ? (u ^ 0x80000000u) : ~u);
}
// packed fp32x2 FMA (sm_100+): 2 FMA per lane per issue
__device__ __forceinline__ unsigned long long ffma2(unsigned long long a,
                                                    unsigned long long b,
                                                    unsigned long long c) {
    unsigned long long d;
    asm("fma.rn.f32x2 %0, %1, %2, %3;" : "=l"(d) : "l"(a), "l"(b), "l"(c));
    return d;
}
__device__ __forceinline__ unsigned long long pk2(float x) {
    unsigned long long r;
    asm("mov.b64 %0, {%1, %1};" : "=l"(r) : "f"(x));
    return r;
}
__device__ __forceinline__ float2 up2(unsigned long long p) {
    float2 r;
    asm("mov.b64 {%0, %1}, %2;" : "=f"(r.x), "=f"(r.y) : "l"(p));
    return r;
}

// ---------------- kernel 0: init encoded-max arrays ----------------
__global__ void init_max_kernel() {
    int i = blockIdx.x * blockDim.x + threadIdx.x;
    if (i < BATCH * TBODY) g_rowmax[i] = 0u;   // below enc of any finite float
    if (i < BATCH * TPUN)  g_colmax[i] = 0u;
}

// ---------------- kernel 1: gate-table GEMM  tbl[v,g] = emb[v,:]·Wih[g,:] + b[g] ----
// M=50000, N=256 per seg, K=300. Tile 128x128, BK=20 (300=15*20), 256 thr,
// 8x8 micro with FFMA2, double-buffered smem + reg-staged global prefetch.
#define BM 128
#define BN 128
#define BK 20
__global__ void __launch_bounds__(256, 2) gemm_tbl_kernel(
    const float* __restrict__ emb,
    const float* __restrict__ W0, const float* __restrict__ W1,
    const float* __restrict__ W2, const float* __restrict__ W3,
    const float* __restrict__ B0, const float* __restrict__ B1,
    const float* __restrict__ B2, const float* __restrict__ B3)
{
    int seg = blockIdx.z;
    const float* W    = (seg == 0) ? W0 : (seg == 1) ? W1 : (seg == 2) ? W2 : W3;
    const float* bias = (seg == 0) ? B0 : (seg == 1) ? B1 : (seg == 2) ? B2 : B3;
    float* out = g_tbl + (size_t)seg * VOCAB * G4;

    int m0 = blockIdx.x * BM;
    int n0 = blockIdx.y * BN;

    __shared__ __align__(16) float As[2][BK][BM + 4];   // 2 x 10.56 KB
    __shared__ __align__(16) float Bs[2][BK][BN + 4];   // 2 x 10.56 KB

    int tid = threadIdx.x;
    int tx = tid & 15, ty = tid >> 4;

    unsigned long long acc[8][4];
#pragma unroll
    for (int i = 0; i < 8; i++)
#pragma unroll
        for (int j = 0; j < 4; j++) acc[i][j] = 0ull;

    float ra[10], rb[10];
    // prefetch chunk 0 into registers
#pragma unroll
    for (int it = 0; it < 10; it++) {
        int l = tid + 256 * it;
        int r = l / BK, kk = l - r * BK;
        int gr = m0 + r;
        ra[it] = (gr < VOCAB) ? emb[(size_t)gr * EMBD + kk] : 0.f;
        rb[it] = W[(size_t)(n0 + r) * EMBD + kk];
    }

    for (int ks = 0; ks < 15; ks++) {
        int buf = ks & 1;
        // stage regs -> smem
#pragma unroll
        for (int it = 0; it < 10; it++) {
            int l = tid + 256 * it;
            int r = l / BK, kk = l - r * BK;
            As[buf][kk][r] = ra[it];
            Bs[buf][kk][r] = rb[it];
        }
        __syncthreads();
        // prefetch next chunk (latency overlapped with compute below)
        if (ks < 14) {
            int k0 = (ks + 1) * BK;
#pragma unroll
            for (int it = 0; it < 10; it++) {
                int l = tid + 256 * it;
                int r = l / BK, kk = l - r * BK;
                int gr = m0 + r;
                ra[it] = (gr < VOCAB) ? emb[(size_t)gr * EMBD + k0 + kk] : 0.f;
                rb[it] = W[(size_t)(n0 + r) * EMBD + k0 + kk];
            }
        }
        // compute on current buffer
#pragma unroll
        for (int kk = 0; kk < BK; kk++) {
            float4 a0 = *(const float4*)&As[buf][kk][ty * 4];
            float4 a1 = *(const float4*)&As[buf][kk][64 + ty * 4];
            ulonglong2 b0 = *(const ulonglong2*)&Bs[buf][kk][tx * 4];
            ulonglong2 b1 = *(const ulonglong2*)&Bs[buf][kk][64 + tx * 4];
            unsigned long long ap[8];
            ap[0] = pk2(a0.x); ap[1] = pk2(a0.y); ap[2] = pk2(a0.z); ap[3] = pk2(a0.w);
            ap[4] = pk2(a1.x); ap[5] = pk2(a1.y); ap[6] = pk2(a1.z); ap[7] = pk2(a1.w);
#pragma unroll
            for (int i = 0; i < 8; i++) {
                acc[i][0] = ffma2(ap[i], b0.x, acc[i][0]);
                acc[i][1] = ffma2(ap[i], b0.y, acc[i][1]);
                acc[i][2] = ffma2(ap[i], b1.x, acc[i][2]);
                acc[i][3] = ffma2(ap[i], b1.y, acc[i][3]);
            }
        }
    }

    float4 bs0 = *(const float4*)&bias[n0 + tx * 4];
    float4 bs1 = *(const float4*)&bias[n0 + 64 + tx * 4];
#pragma unroll
    for (int i = 0; i < 8; i++) {
        int r = m0 + ty * 4 + (i & 3) + (i >> 2) * 64;
        if (r < VOCAB) {
            float2 v0 = up2(acc[i][0]), v1 = up2(acc[i][1]);
            float2 v2 = up2(acc[i][2]), v3 = up2(acc[i][3]);
            float4 o0 = make_float4(v0.x + bs0.x, v0.y + bs0.y, v1.x + bs0.z, v1.y + bs0.w);
            float4 o1 = make_float4(v2.x + bs1.x, v2.y + bs1.y, v3.x + bs1.z, v3.y + bs1.w);
            *(float4*)&out[(size_t)r * G4 + n0 + tx * 4] = o0;
            *(float4*)&out[(size_t)r * G4 + n0 + 64 + tx * 4] = o1;
        }
    }
}

// ---------------- kernel 2: LSTM (4 runs x 128 batches = 512 blocks, 256 thr) ----------------
__global__ void __launch_bounds__(256) lstm_kernel(
    const int* __restrict__ body_idx, const int* __restrict__ pun_idx,
    const float* __restrict__ Whh0, const float* __restrict__ Whh1,
    const float* __restrict__ Whh2, const float* __restrict__ Whh3)
{
    int blk = blockIdx.x;
    int seg = blk >> 7;
    int b   = blk & 127;
    bool isBody = (seg < 2);
    bool isFwd  = ((seg & 1) == 0);
    int T = isBody ? TBODY : TPUN;
    const int* idx = isBody ? (body_idx + b * TBODY) : (pun_idx + b * TPUN);
    const float* Whh = (seg == 0) ? Whh0 : (seg == 1) ? Whh1 : (seg == 2) ? Whh2 : Whh3;
    const float* tbl = g_tbl + (size_t)seg * VOCAB * G4;
    float* out = isBody ? (g_bodyM + (size_t)b * TBODY * D2)
                        : (g_punM  + (size_t)b * TPUN  * D2);
    int off = isFwd ? 0 : HID;

    __shared__ int idx_s[TBODY];
    __shared__ __align__(16) float hs[HID];
    __shared__ float gs[G4];
    __shared__ int len_s;

    int tid = threadIdx.x;
    int g = tid;

    if (tid == 0) len_s = 0;
    if (tid < HID) hs[tid] = 0.f;
    __syncthreads();

    int cnt = 0;
    for (int t = tid; t < T; t += 256) {
        int v = idx[t];
        idx_s[t] = v;
        cnt += (v != 0);
    }
#pragma unroll
    for (int o = 16; o; o >>= 1) cnt += __shfl_xor_sync(0xFFFFFFFFu, cnt, o);
    if ((tid & 31) == 0) atomicAdd(&len_s, cnt);
    __syncthreads();
    int len = len_s;

    float w[HID];
#pragma unroll
    for (int j = 0; j < HID; j++) w[j] = Whh[(size_t)g * HID + j];

    float c = 0.f;
    float x1 = 0.f, x2 = 0.f;
    if (len > 0) x1 = tbl[(size_t)idx_s[isFwd ? 0 : (len - 1)] * G4 + g];
    if (len > 1) x2 = tbl[(size_t)idx_s[isFwd ? 1 : (len - 2)] * G4 + g];

    const float4* hv4 = (const float4*)hs;
    for (int t = 0; t < len; t++) {
        float xs = x1;
        x1 = x2;
        if (t + 2 < len) {
            int p2 = isFwd ? (t + 2) : (len - 3 - t);
            x2 = tbl[(size_t)idx_s[p2] * G4 + g];
        }
        // 4-chain dot product: dependency depth 16 instead of 64
        float a0 = xs, a1 = 0.f, a2 = 0.f, a3 = 0.f;
#pragma unroll
        for (int jj = 0; jj < 16; jj++) {
            float4 h4 = hv4[jj];
            a0 += w[4 * jj + 0] * h4.x;
            a1 += w[4 * jj + 1] * h4.y;
            a2 += w[4 * jj + 2] * h4.z;
            a3 += w[4 * jj + 3] * h4.w;
        }
        float pre = (a0 + a1) + (a2 + a3);
        // gate order i,f,g,o ; g-gate tanh, others sigmoid
        float act = (g >= 128 && g < 192) ? tanhf(pre)
                                          : 1.f / (1.f + __expf(-pre));
        gs[g] = act;
        __syncthreads();
        if (g < HID) {
            float cn = gs[HID + g] * c + gs[g] * gs[128 + g];
            c = cn;
            float h = gs[192 + g] * tanhf(cn);
            hs[g] = h;
            int pos = isFwd ? t : (len - 1 - t);
            out[(size_t)pos * D2 + off + g] = h;
        }
        __syncthreads();
    }
    for (int l = tid; l < (T - len) * HID; l += 256) {
        int tpos = len + l / HID;
        int j = l - (l / HID) * HID;
        out[(size_t)tpos * D2 + off + j] = 0.f;
    }
}

// ---------------- kernel 3: alignment maxes (double-buffered GEMM form) ----------------
// grid = 128 batches * 4 t-chunks * 2 p-chunks = 1024 blocks, 256 thr.
// Tile 128t x 128p, BK=16 over d; smem ~36 KB -> 2 blocks/SM.
#define ABK 16
__global__ void __launch_bounds__(256, 2) align_kernel(const float* __restrict__ w_u)
{
    int bx = blockIdx.x;
    int b  = bx >> 3;
    int tc = (bx >> 1) & 3;
    int pc = bx & 1;
    int t0 = tc * 128;
    int p0 = pc * 128;
    const float* bodyM = g_bodyM + (size_t)b * TBODY * D2;
    const float* punM  = g_punM  + (size_t)b * TPUN  * D2;

    __shared__ __align__(16) float Bs[2][ABK][132];   // [d][t], w3 pre-applied
    __shared__ __align__(16) float Ps[2][ABK][132];   // [d][p]
    __shared__ float a1s[128], a2s[128];
    __shared__ unsigned rms[128], cms[128];

    int tid = threadIdx.x;
    int tx = tid & 15, ty = tid >> 4;
    int warp = tid >> 5, lane = tid & 31;
    int q  = tid & 3;        // d-quad within chunk
    int rr = tid >> 2;       // row 0..63 (+64 on second pass)

    if (tid < 128) { rms[tid] = 0u; cms[tid] = 0u; }
    __syncthreads();

    // a1 (w1·body row) for local 128 t rows; a2 (w2·pun row) for local 128 p rows
    for (int r = warp; r < 128; r += 8) {
        const float* row = bodyM + (size_t)(t0 + r) * D2;
        float s = 0.f;
        for (int d = lane; d < D2; d += 32) s += row[d] * w_u[d];
#pragma unroll
        for (int o = 16; o; o >>= 1) s += __shfl_xor_sync(0xFFFFFFFFu, s, o);
        if (lane == 0) a1s[r] = s;
    }
    for (int r = warp; r < 128; r += 8) {
        const float* row = punM + (size_t)(p0 + r) * D2;
        float s = 0.f;
        for (int d = lane; d < D2; d += 32) s += row[d] * w_u[D2 + d];
#pragma unroll
        for (int o = 16; o; o >>= 1) s += __shfl_xor_sync(0xFFFFFFFFu, s, o);
        if (lane == 0) a2s[r] = s;
    }

    unsigned long long acc[8][4];
#pragma unroll
    for (int i = 0; i < 8; i++)
#pragma unroll
        for (int j = 0; j < 4; j++) acc[i][j] = 0ull;

    // prefetch chunk 0
    float4 bv[2], pv[2];
    {
        float4 w3v = *(const float4*)&w_u[2 * D2 + 4 * q];
#pragma unroll
        for (int i = 0; i < 2; i++) {
            int r = rr + 64 * i;
            float4 v = *(const float4*)&bodyM[(size_t)(t0 + r) * D2 + 4 * q];
            bv[i] = make_float4(v.x * w3v.x, v.y * w3v.y, v.z * w3v.z, v.w * w3v.w);
            pv[i] = *(const float4*)&punM[(size_t)(p0 + r) * D2 + 4 * q];
        }
    }

    for (int kc = 0; kc < 8; kc++) {
        int buf = kc & 1;
#pragma unroll
        for (int i = 0; i < 2; i++) {
            int r = rr + 64 * i;
            Bs[buf][4 * q + 0][r] = bv[i].x;
            Bs[buf][4 * q + 1][r] = bv[i].y;
            Bs[buf][4 * q + 2][r] = bv[i].z;
            Bs[buf][4 * q + 3][r] = bv[i].w;
            Ps[buf][4 * q + 0][r] = pv[i].x;
            Ps[buf][4 * q + 1][r] = pv[i].y;
            Ps[buf][4 * q + 2][r] = pv[i].z;
            Ps[buf][4 * q + 3][r] = pv[i].w;
        }
        __syncthreads();
        if (kc < 7) {
            int d0 = (kc + 1) * ABK;
            float4 w3v = *(const float4*)&w_u[2 * D2 + d0 + 4 * q];
#pragma unroll
            for (int i = 0; i < 2; i++) {
                int r = rr + 64 * i;
                float4 v = *(const float4*)&bodyM[(size_t)(t0 + r) * D2 + d0 + 4 * q];
                bv[i] = make_float4(v.x * w3v.x, v.y * w3v.y, v.z * w3v.z, v.w * w3v.w);
                pv[i] = *(const float4*)&punM[(size_t)(p0 + r) * D2 + d0 + 4 * q];
            }
        }
#pragma unroll
        for (int d = 0; d < ABK; d++) {
            float4 a0 = *(const float4*)&Bs[buf][d][ty * 4];
            float4 a1 = *(const float4*)&Bs[buf][d][64 + ty * 4];
            ulonglong2 b0 = *(const ulonglong2*)&Ps[buf][d][tx * 4];
            ulonglong2 b1 = *(const ulonglong2*)&Ps[buf][d][64 + tx * 4];
            unsigned long long ap[8];
            ap[0] = pk2(a0.x); ap[1] = pk2(a0.y); ap[2] = pk2(a0.z); ap[3] = pk2(a0.w);
            ap[4] = pk2(a1.x); ap[5] = pk2(a1.y); ap[6] = pk2(a1.z); ap[7] = pk2(a1.w);
#pragma unroll
            for (int i = 0; i < 8; i++) {
                acc[i][0] = ffma2(ap[i], b0.x, acc[i][0]);
                acc[i][1] = ffma2(ap[i], b0.y, acc[i][1]);
                acc[i][2] = ffma2(ap[i], b1.x, acc[i][2]);
                acc[i][3] = ffma2(ap[i], b1.y, acc[i][3]);
            }
        }
    }

    // combine with a1/a2, reduce maxes
    float rmax[8], cmax[8];
#pragma unroll
    for (int i = 0; i < 8; i++) { rmax[i] = -1e30f; cmax[i] = -1e30f; }
#pragma unroll
    for (int i = 0; i < 8; i++) {
        int trow = ty * 4 + (i & 3) + (i >> 2) * 64;
        float a1v = a1s[trow];
#pragma unroll
        for (int jp = 0; jp < 4; jp++) {
            float2 v = up2(acc[i][jp]);
            int c0 = tx * 4 + (jp >> 1) * 64 + (jp & 1) * 2;
            float v0 = v.x + a1v + a2s[c0];
            float v1 = v.y + a1v + a2s[c0 + 1];
            rmax[i] = fmaxf(rmax[i], fmaxf(v0, v1));
            int jj = (jp >> 1) * 4 + (jp & 1) * 2;
            cmax[jj]     = fmaxf(cmax[jj], v0);
            cmax[jj + 1] = fmaxf(cmax[jj + 1], v1);
        }
    }
#pragma unroll
    for (int i = 0; i < 8; i++) {
        int trow = ty * 4 + (i & 3) + (i >> 2) * 64;
        atomicMax(&rms[trow], enc_f(rmax[i]));
    }
#pragma unroll
    for (int j = 0; j < 8; j++) {
        int col = tx * 4 + (j >> 2) * 64 + (j & 3);
        atomicMax(&cms[col], enc_f(cmax[j]));
    }
    __syncthreads();

    if (tid < 128) {
        atomicMax(&g_rowmax[b * TBODY + t0 + tid], rms[tid]);
        atomicMax(&g_colmax[b * TPUN + p0 + tid], cms[tid]);
    }
}

// ---------------- kernel 4: softmaxes + weighted sums + final linear ----------------
__global__ void __launch_bounds__(256) final_kernel(
    const float* __restrict__ Wd, const float* __restrict__ bd,
    float* __restrict__ outp)
{
    int b = blockIdx.x;
    int tid = threadIdx.x;
    int lane = tid & 31, warp = tid >> 5;

    __shared__ float attb[TBODY];
    __shared__ float attp[TPUN];
    __shared__ float feat[G4];
    __shared__ float sred[8];

    // softmax over rowmax[512]
    float v0 = dec_f(g_rowmax[b * TBODY + tid]);
    float v1 = dec_f(g_rowmax[b * TBODY + 256 + tid]);
    float m = fmaxf(v0, v1);
#pragma unroll
    for (int o = 16; o; o >>= 1) m = fmaxf(m, __shfl_xor_sync(0xFFFFFFFFu, m, o));
    if (lane == 0) sred[warp] = m;
    __syncthreads();
    float M = sred[0];
#pragma unroll
    for (int w = 1; w < 8; w++) M = fmaxf(M, sred[w]);
    __syncthreads();
    float e0 = __expf(v0 - M), e1 = __expf(v1 - M);
    float ss = e0 + e1;
#pragma unroll
    for (int o = 16; o; o >>= 1) ss += __shfl_xor_sync(0xFFFFFFFFu, ss, o);
    if (lane == 0) sred[warp] = ss;
    __syncthreads();
    float S = 0.f;
#pragma unroll
    for (int w = 0; w < 8; w++) S += sred[w];
    __syncthreads();
    attb[tid] = e0 / S;
    attb[256 + tid] = e1 / S;

    // softmax over colmax[256]
    float u = dec_f(g_colmax[b * TPUN + tid]);
    float m2 = u;
#pragma unroll
    for (int o = 16; o; o >>= 1) m2 = fmaxf(m2, __shfl_xor_sync(0xFFFFFFFFu, m2, o));
    if (lane == 0) sred[warp] = m2;
    __syncthreads();
    float M2 = sred[0];
#pragma unroll
    for (int w = 1; w < 8; w++) M2 = fmaxf(M2, sred[w]);
    __syncthreads();
    float e2 = __expf(u - M2);
    float ss2 = e2;
#pragma unroll
    for (int o = 16; o; o >>= 1) ss2 += __shfl_xor_sync(0xFFFFFFFFu, ss2, o);
    if (lane == 0) sred[warp] = ss2;
    __syncthreads();
    float S2 = 0.f;
#pragma unroll
    for (int w = 0; w < 8; w++) S2 += sred[w];
    __syncthreads();
    attp[tid] = e2 / S2;
    __syncthreads();

    // weighted sums -> feat[256]
    if (tid < D2) {
        const float* bm = g_bodyM + (size_t)b * TBODY * D2 + tid;
        float s = 0.f;
#pragma unroll 8
        for (int t = 0; t < TBODY; t++) s += bm[(size_t)t * D2] * attb[t];
        feat[tid] = s;
    } else {
        int d = tid - D2;
        const float* pm = g_punM + (size_t)b * TPUN * D2 + d;
        float s = 0.f;
#pragma unroll 8
        for (int p = 0; p < TPUN; p++) s += pm[(size_t)p * D2] * attp[p];
        feat[D2 + d] = s;
    }
    __syncthreads();

    if (tid < 3) {
        float s = bd[tid];
        for (int k = 0; k < G4; k++) s += feat[k] * Wd[tid * G4 + k];
        outp[b * 3 + tid] = s;
    }
}

// ---------------- host launcher ----------------
extern "C" void kernel_launch(void* const* d_in, const int* in_sizes, int n_in,
                              void* d_out, int out_size)
{
    // Disambiguate input ordering: signature order has bWih_f (76800) at index 3,
    // dict-insertion order has w_u (384) at index 3.
    int base, iwu, iwd, ibd;
    if (in_sizes[3] == 76800) { base = 3; iwu = 15; iwd = 16; ibd = 17; }
    else                      { base = 6; iwu = 3;  iwd = 4;  ibd = 5;  }

    const int*   body_idx = (const int*)d_in[0];
    const int*   pun_idx  = (const int*)d_in[1];
    const float* emb      = (const float*)d_in[2];

    const float* Wih[4]; const float* Whh[4]; const float* bv[4];
    for (int s = 0; s < 4; s++) {
        Wih[s] = (const float*)d_in[base + 3 * s + 0];
        Whh[s] = (const float*)d_in[base + 3 * s + 1];
        bv[s]  = (const float*)d_in[base + 3 * s + 2];
    }
    const float* w_u = (const float*)d_in[iwu];
    const float* Wd  = (const float*)d_in[iwd];
    const float* bd  = (const float*)d_in[ibd];
    float* outp = (float*)d_out;

    init_max_kernel<<<(BATCH * TBODY + 255) / 256, 256>>>();

    dim3 gg((VOCAB + BM - 1) / BM, G4 / BN, 4);
    gemm_tbl_kernel<<<gg, 256>>>(emb, Wih[0], Wih[1], Wih[2], Wih[3],
                                 bv[0], bv[1], bv[2], bv[3]);

    lstm_kernel<<<512, 256>>>(body_idx, pun_idx, Whh[0], Whh[1], Whh[2], Whh[3]);

    align_kernel<<<BATCH * 8, 256>>>(w_u);

    final_kernel<<<BATCH, 256>>>(Wd, bd, outp);
    (void)n_in; (void)out_size;
}

// round 8
// speedup vs baseline: 1.3810x; 1.1825x over previous
#include <cuda_runtime.h>
#include <cstdint>

#define VOCAB 50000
#define EMBD  300
#define HID   64
#define G4    256      // 4*H
#define D2    128      // 2*H
#define BATCH 128
#define TBODY 512
#define TPUN  256

// ---------------- scratch (static device arrays: allocation-free) ----------------
__device__ float    g_tbl[(size_t)4 * VOCAB * G4];          // 204.8 MB gate tables
__device__ float    g_bodyM[(size_t)BATCH * TBODY * D2];    // 33.5 MB
__device__ float    g_punM[(size_t)BATCH * TPUN * D2];      // 16.8 MB
__device__ unsigned g_rowmax[BATCH * TBODY];                // ordered-int encoded
__device__ unsigned g_colmax[BATCH * TPUN];                 // ordered-int encoded
__device__ int      g_flag[2][VOCAB];                       // 0 body, 1 pun
__device__ int      g_list[2][VOCAB];
__device__ int      g_cnt[2];

// ---------------- helpers ----------------
__device__ __forceinline__ unsigned enc_f(float f) {
    unsigned u = __float_as_uint(f);
    return (u & 0x80000000u) ? ~u : (u | 0x80000000u);
}
__device__ __forceinline__ float dec_f(unsigned u) {
    return __uint_as_float((u & 0x80000000u) ? (u ^ 0x80000000u) : ~u);
}
// packed fp32x2 FMA (sm_100+): 2 FMA per lane per issue
__device__ __forceinline__ unsigned long long ffma2(unsigned long long a,
                                                    unsigned long long b,
                                                    unsigned long long c) {
    unsigned long long d;
    asm("fma.rn.f32x2 %0, %1, %2, %3;" : "=l"(d) : "l"(a), "l"(b), "l"(c));
    return d;
}
__device__ __forceinline__ unsigned long long pk2(float x) {
    unsigned long long r;
    asm("mov.b64 %0, {%1, %1};" : "=l"(r) : "f"(x));
    return r;
}
__device__ __forceinline__ float2 up2(unsigned long long p) {
    float2 r;
    asm("mov.b64 {%0, %1}, %2;" : "=f"(r.x), "=f"(r.y) : "l"(p));
    return r;
}

// ---------------- kernel 0: zero flags/counters + encoded-max arrays ----------------
__global__ void zero_kernel() {
    int i = blockIdx.x * blockDim.x + threadIdx.x;   // grid covers 65536
    if (i < VOCAB) { g_flag[0][i] = 0; g_flag[1][i] = 0; }
    if (i == 0) { g_cnt[0] = 0; g_cnt[1] = 0; }
    if (i < BATCH * TBODY) g_rowmax[i] = 0u;
    if (i < BATCH * TPUN)  g_colmax[i] = 0u;
}

// ---------------- kernel 0b: mark used vocab ids, warp-aggregated compaction ------
__global__ void mark_kernel(const int* __restrict__ body_idx,
                            const int* __restrict__ pun_idx) {
    int i = blockIdx.x * blockDim.x + threadIdx.x;   // 98304 threads
    int which, v;
    if (i < BATCH * TBODY) { which = 0; v = body_idx[i]; }
    else                   { which = 1; v = pun_idx[i - BATCH * TBODY]; }
    // each warp is entirely one type (boundary 65536 is warp-aligned)
    bool isnew = (atomicExch(&g_flag[which][v], 1) == 0);
    unsigned mask = __ballot_sync(0xFFFFFFFFu, isnew);
    int n = __popc(mask);
    if (n) {
        int lane = threadIdx.x & 31;
        int leader = __ffs(mask) - 1;
        int base = 0;
        if (lane == leader) base = atomicAdd(&g_cnt[which], n);
        base = __shfl_sync(0xFFFFFFFFu, base, leader);
        if (isnew) g_list[which][base + __popc(mask & ((1u << lane) - 1))] = v;
    }
}

// ---------------- kernel 1: gate-table GEMM over USED vocab rows ------------------
// grid (391, 4, 2): x = m-block over used list, y = 128-col block of fused N=512
// (y>>1 = direction, y&1 = col half), z = text type (0 body, 1 pun).
// Tile 128x128, BK=20, 256 thr, 8x8 FFMA2 micro, double-buffered smem,
// A-side stored pre-duplicated as f32x2 in smem (no pk2 MOVs in inner loop).
#define BM 128
#define BN 128
#define BK 20
__global__ void __launch_bounds__(256, 2) gemm_tbl_kernel(
    const float* __restrict__ emb,
    const float* __restrict__ W0, const float* __restrict__ W1,
    const float* __restrict__ W2, const float* __restrict__ W3,
    const float* __restrict__ B0, const float* __restrict__ B1,
    const float* __restrict__ B2, const float* __restrict__ B3)
{
    int z = blockIdx.z;
    int cnt = g_cnt[z];
    int m0 = blockIdx.x * BM;
    if (m0 >= cnt) return;
    int y = blockIdx.y;
    int dir = y >> 1;
    int n0 = (y & 1) * 128;          // col offset within this direction's 256
    int seg = z * 2 + dir;
    const float* W    = (seg == 0) ? W0 : (seg == 1) ? W1 : (seg == 2) ? W2 : W3;
    const float* bias = (seg == 0) ? B0 : (seg == 1) ? B1 : (seg == 2) ? B2 : B3;
    float* out = g_tbl + (size_t)seg * VOCAB * G4;

    __shared__ __align__(16) unsigned long long As[2][BK][BM + 2];  // dup f32x2
    __shared__ __align__(16) float Bs[2][BK][BN + 4];
    __shared__ int ids[BM];

    int tid = threadIdx.x;
    int tx = tid & 15, ty = tid >> 4;

    if (tid < BM) ids[tid] = (m0 + tid < cnt) ? g_list[z][m0 + tid] : 0;
    __syncthreads();

    unsigned long long acc[8][4];
#pragma unroll
    for (int i = 0; i < 8; i++)
#pragma unroll
        for (int j = 0; j < 4; j++) acc[i][j] = 0ull;

    float ra[10], rb[10];
#pragma unroll
    for (int it = 0; it < 10; it++) {
        int l = tid + 256 * it;
        int r = l / BK, kk = l - r * BK;
        ra[it] = emb[(size_t)ids[r] * EMBD + kk];
        rb[it] = W[(size_t)(n0 + r) * EMBD + kk];
    }

    for (int ks = 0; ks < 15; ks++) {
        int buf = ks & 1;
#pragma unroll
        for (int it = 0; it < 10; it++) {
            int l = tid + 256 * it;
            int r = l / BK, kk = l - r * BK;
            As[buf][kk][r] = pk2(ra[it]);
            Bs[buf][kk][r] = rb[it];
        }
        __syncthreads();
        if (ks < 14) {
            int k0 = (ks + 1) * BK;
#pragma unroll
            for (int it = 0; it < 10; it++) {
                int l = tid + 256 * it;
                int r = l / BK, kk = l - r * BK;
                ra[it] = emb[(size_t)ids[r] * EMBD + k0 + kk];
                rb[it] = W[(size_t)(n0 + r) * EMBD + k0 + kk];
            }
        }
#pragma unroll
        for (int kk = 0; kk < BK; kk++) {
            ulonglong2 a01 = *(const ulonglong2*)&As[buf][kk][ty * 4];
            ulonglong2 a23 = *(const ulonglong2*)&As[buf][kk][ty * 4 + 2];
            ulonglong2 a45 = *(const ulonglong2*)&As[buf][kk][64 + ty * 4];
            ulonglong2 a67 = *(const ulonglong2*)&As[buf][kk][64 + ty * 4 + 2];
            ulonglong2 b0 = *(const ulonglong2*)&Bs[buf][kk][tx * 4];
            ulonglong2 b1 = *(const ulonglong2*)&Bs[buf][kk][64 + tx * 4];
            unsigned long long ap[8];
            ap[0] = a01.x; ap[1] = a01.y; ap[2] = a23.x; ap[3] = a23.y;
            ap[4] = a45.x; ap[5] = a45.y; ap[6] = a67.x; ap[7] = a67.y;
#pragma unroll
            for (int i = 0; i < 8; i++) {
                acc[i][0] = ffma2(ap[i], b0.x, acc[i][0]);
                acc[i][1] = ffma2(ap[i], b0.y, acc[i][1]);
                acc[i][2] = ffma2(ap[i], b1.x, acc[i][2]);
                acc[i][3] = ffma2(ap[i], b1.y, acc[i][3]);
            }
        }
    }

    float4 bs0 = *(const float4*)&bias[n0 + tx * 4];
    float4 bs1 = *(const float4*)&bias[n0 + 64 + tx * 4];
#pragma unroll
    for (int i = 0; i < 8; i++) {
        int r = ids[ty * 4 + (i & 3) + (i >> 2) * 64];
        float2 v0 = up2(acc[i][0]), v1 = up2(acc[i][1]);
        float2 v2 = up2(acc[i][2]), v3 = up2(acc[i][3]);
        float4 o0 = make_float4(v0.x + bs0.x, v0.y + bs0.y, v1.x + bs0.z, v1.y + bs0.w);
        float4 o1 = make_float4(v2.x + bs1.x, v2.y + bs1.y, v3.x + bs1.z, v3.y + bs1.w);
        *(float4*)&out[(size_t)r * G4 + n0 + tx * 4] = o0;
        *(float4*)&out[(size_t)r * G4 + n0 + 64 + tx * 4] = o1;
    }
}

// ---------------- kernel 2: LSTM (4 runs x 128 batches = 512 blocks, 256 thr) ----------------
__global__ void __launch_bounds__(256) lstm_kernel(
    const int* __restrict__ body_idx, const int* __restrict__ pun_idx,
    const float* __restrict__ Whh0, const float* __restrict__ Whh1,
    const float* __restrict__ Whh2, const float* __restrict__ Whh3)
{
    int blk = blockIdx.x;
    int seg = blk >> 7;
    int b   = blk & 127;
    bool isBody = (seg < 2);
    bool isFwd  = ((seg & 1) == 0);
    int T = isBody ? TBODY : TPUN;
    const int* idx = isBody ? (body_idx + b * TBODY) : (pun_idx + b * TPUN);
    const float* Whh = (seg == 0) ? Whh0 : (seg == 1) ? Whh1 : (seg == 2) ? Whh2 : Whh3;
    const float* tbl = g_tbl + (size_t)seg * VOCAB * G4;
    float* out = isBody ? (g_bodyM + (size_t)b * TBODY * D2)
                        : (g_punM  + (size_t)b * TPUN  * D2);
    int off = isFwd ? 0 : HID;

    __shared__ int idx_s[TBODY];
    __shared__ __align__(16) float hs[HID];
    __shared__ float gs[G4];
    __shared__ int len_s;

    int tid = threadIdx.x;
    int g = tid;

    if (tid == 0) len_s = 0;
    if (tid < HID) hs[tid] = 0.f;
    __syncthreads();

    int cnt = 0;
    for (int t = tid; t < T; t += 256) {
        int v = idx[t];
        idx_s[t] = v;
        cnt += (v != 0);
    }
#pragma unroll
    for (int o = 16; o; o >>= 1) cnt += __shfl_xor_sync(0xFFFFFFFFu, cnt, o);
    if ((tid & 31) == 0) atomicAdd(&len_s, cnt);
    __syncthreads();
    int len = len_s;

    float w[HID];
#pragma unroll
    for (int j = 0; j < HID; j++) w[j] = Whh[(size_t)g * HID + j];

    float c = 0.f;
    float x1 = 0.f, x2 = 0.f;
    if (len > 0) x1 = tbl[(size_t)idx_s[isFwd ? 0 : (len - 1)] * G4 + g];
    if (len > 1) x2 = tbl[(size_t)idx_s[isFwd ? 1 : (len - 2)] * G4 + g];

    const float4* hv4 = (const float4*)hs;
    for (int t = 0; t < len; t++) {
        float xs = x1;
        x1 = x2;
        if (t + 2 < len) {
            int p2 = isFwd ? (t + 2) : (len - 3 - t);
            x2 = tbl[(size_t)idx_s[p2] * G4 + g];
        }
        // 4-chain dot product: dependency depth 16 instead of 64
        float a0 = xs, a1 = 0.f, a2 = 0.f, a3 = 0.f;
#pragma unroll
        for (int jj = 0; jj < 16; jj++) {
            float4 h4 = hv4[jj];
            a0 += w[4 * jj + 0] * h4.x;
            a1 += w[4 * jj + 1] * h4.y;
            a2 += w[4 * jj + 2] * h4.z;
            a3 += w[4 * jj + 3] * h4.w;
        }
        float pre = (a0 + a1) + (a2 + a3);
        // gate order i,f,g,o ; g-gate tanh, others sigmoid
        float act = (g >= 128 && g < 192) ? tanhf(pre)
                                          : 1.f / (1.f + __expf(-pre));
        gs[g] = act;
        __syncthreads();
        if (g < HID) {
            float cn = gs[HID + g] * c + gs[g] * gs[128 + g];
            c = cn;
            float h = gs[192 + g] * tanhf(cn);
            hs[g] = h;
            int pos = isFwd ? t : (len - 1 - t);
            out[(size_t)pos * D2 + off + g] = h;
        }
        __syncthreads();
    }
    for (int l = tid; l < (T - len) * HID; l += 256) {
        int tpos = len + l / HID;
        int j = l - (l / HID) * HID;
        out[(size_t)tpos * D2 + off + j] = 0.f;
    }
}

// ---------------- kernel 3: alignment maxes (double-buffered GEMM form) ----------------
// grid = 128 batches * 4 t-chunks * 2 p-chunks = 1024 blocks, 256 thr.
// Tile 128t x 128p, BK=16 over d; body side stored pre-duplicated f32x2 in smem.
#define ABK 16
__global__ void __launch_bounds__(256, 2) align_kernel(const float* __restrict__ w_u)
{
    int bx = blockIdx.x;
    int b  = bx >> 3;
    int tc = (bx >> 1) & 3;
    int pc = bx & 1;
    int t0 = tc * 128;
    int p0 = pc * 128;
    const float* bodyM = g_bodyM + (size_t)b * TBODY * D2;
    const float* punM  = g_punM  + (size_t)b * TPUN  * D2;

    __shared__ __align__(16) unsigned long long Bsu[2][ABK][130];  // [d][t] dup, w3 applied
    __shared__ __align__(16) float Ps[2][ABK][132];                // [d][p]
    __shared__ float a1s[128], a2s[128];
    __shared__ unsigned rms[128], cms[128];

    int tid = threadIdx.x;
    int tx = tid & 15, ty = tid >> 4;
    int warp = tid >> 5, lane = tid & 31;
    int q  = tid & 3;        // d-quad within chunk
    int rr = tid >> 2;       // row 0..63 (+64 on second pass)

    if (tid < 128) { rms[tid] = 0u; cms[tid] = 0u; }
    __syncthreads();

    // a1 (w1·body row) for local 128 t rows; a2 (w2·pun row) for local 128 p rows
    for (int r = warp; r < 128; r += 8) {
        const float* row = bodyM + (size_t)(t0 + r) * D2;
        float s = 0.f;
        for (int d = lane; d < D2; d += 32) s += row[d] * w_u[d];
#pragma unroll
        for (int o = 16; o; o >>= 1) s += __shfl_xor_sync(0xFFFFFFFFu, s, o);
        if (lane == 0) a1s[r] = s;
    }
    for (int r = warp; r < 128; r += 8) {
        const float* row = punM + (size_t)(p0 + r) * D2;
        float s = 0.f;
        for (int d = lane; d < D2; d += 32) s += row[d] * w_u[D2 + d];
#pragma unroll
        for (int o = 16; o; o >>= 1) s += __shfl_xor_sync(0xFFFFFFFFu, s, o);
        if (lane == 0) a2s[r] = s;
    }

    unsigned long long acc[8][4];
#pragma unroll
    for (int i = 0; i < 8; i++)
#pragma unroll
        for (int j = 0; j < 4; j++) acc[i][j] = 0ull;

    // prefetch chunk 0
    float4 bv[2], pv[2];
    {
        float4 w3v = *(const float4*)&w_u[2 * D2 + 4 * q];
#pragma unroll
        for (int i = 0; i < 2; i++) {
            int r = rr + 64 * i;
            float4 v = *(const float4*)&bodyM[(size_t)(t0 + r) * D2 + 4 * q];
            bv[i] = make_float4(v.x * w3v.x, v.y * w3v.y, v.z * w3v.z, v.w * w3v.w);
            pv[i] = *(const float4*)&punM[(size_t)(p0 + r) * D2 + 4 * q];
        }
    }

    for (int kc = 0; kc < 8; kc++) {
        int buf = kc & 1;
#pragma unroll
        for (int i = 0; i < 2; i++) {
            int r = rr + 64 * i;
            Bsu[buf][4 * q + 0][r] = pk2(bv[i].x);
            Bsu[buf][4 * q + 1][r] = pk2(bv[i].y);
            Bsu[buf][4 * q + 2][r] = pk2(bv[i].z);
            Bsu[buf][4 * q + 3][r] = pk2(bv[i].w);
            Ps[buf][4 * q + 0][r] = pv[i].x;
            Ps[buf][4 * q + 1][r] = pv[i].y;
            Ps[buf][4 * q + 2][r] = pv[i].z;
            Ps[buf][4 * q + 3][r] = pv[i].w;
        }
        __syncthreads();
        if (kc < 7) {
            int d0 = (kc + 1) * ABK;
            float4 w3v = *(const float4*)&w_u[2 * D2 + d0 + 4 * q];
#pragma unroll
            for (int i = 0; i < 2; i++) {
                int r = rr + 64 * i;
                float4 v = *(const float4*)&bodyM[(size_t)(t0 + r) * D2 + d0 + 4 * q];
                bv[i] = make_float4(v.x * w3v.x, v.y * w3v.y, v.z * w3v.z, v.w * w3v.w);
                pv[i] = *(const float4*)&punM[(size_t)(p0 + r) * D2 + d0 + 4 * q];
            }
        }
#pragma unroll
        for (int d = 0; d < ABK; d++) {
            ulonglong2 a01 = *(const ulonglong2*)&Bsu[buf][d][ty * 4];
            ulonglong2 a23 = *(const ulonglong2*)&Bsu[buf][d][ty * 4 + 2];
            ulonglong2 a45 = *(const ulonglong2*)&Bsu[buf][d][64 + ty * 4];
            ulonglong2 a67 = *(const ulonglong2*)&Bsu[buf][d][64 + ty * 4 + 2];
            ulonglong2 b0 = *(const ulonglong2*)&Ps[buf][d][tx * 4];
            ulonglong2 b1 = *(const ulonglong2*)&Ps[buf][d][64 + tx * 4];
            unsigned long long ap[8];
            ap[0] = a01.x; ap[1] = a01.y; ap[2] = a23.x; ap[3] = a23.y;
            ap[4] = a45.x; ap[5] = a45.y; ap[6] = a67.x; ap[7] = a67.y;
#pragma unroll
            for (int i = 0; i < 8; i++) {
                acc[i][0] = ffma2(ap[i], b0.x, acc[i][0]);
                acc[i][1] = ffma2(ap[i], b0.y, acc[i][1]);
                acc[i][2] = ffma2(ap[i], b1.x, acc[i][2]);
                acc[i][3] = ffma2(ap[i], b1.y, acc[i][3]);
            }
        }
    }

    // combine with a1/a2, reduce maxes
    float rmax[8], cmax[8];
#pragma unroll
    for (int i = 0; i < 8; i++) { rmax[i] = -1e30f; cmax[i] = -1e30f; }
#pragma unroll
    for (int i = 0; i < 8; i++) {
        int trow = ty * 4 + (i & 3) + (i >> 2) * 64;
        float a1v = a1s[trow];
#pragma unroll
        for (int jp = 0; jp < 4; jp++) {
            float2 v = up2(acc[i][jp]);
            int c0 = tx * 4 + (jp >> 1) * 64 + (jp & 1) * 2;
            float v0 = v.x + a1v + a2s[c0];
            float v1 = v.y + a1v + a2s[c0 + 1];
            rmax[i] = fmaxf(rmax[i], fmaxf(v0, v1));
            int jj = (jp >> 1) * 4 + (jp & 1) * 2;
            cmax[jj]     = fmaxf(cmax[jj], v0);
            cmax[jj + 1] = fmaxf(cmax[jj + 1], v1);
        }
    }
#pragma unroll
    for (int i = 0; i < 8; i++) {
        int trow = ty * 4 + (i & 3) + (i >> 2) * 64;
        atomicMax(&rms[trow], enc_f(rmax[i]));
    }
#pragma unroll
    for (int j = 0; j < 8; j++) {
        int col = tx * 4 + (j >> 2) * 64 + (j & 3);
        atomicMax(&cms[col], enc_f(cmax[j]));
    }
    __syncthreads();

    if (tid < 128) {
        atomicMax(&g_rowmax[b * TBODY + t0 + tid], rms[tid]);
        atomicMax(&g_colmax[b * TPUN + p0 + tid], cms[tid]);
    }
}

// ---------------- kernel 4: softmaxes + weighted sums + final linear ----------------
__global__ void __launch_bounds__(256) final_kernel(
    const float* __restrict__ Wd, const float* __restrict__ bd,
    float* __restrict__ outp)
{
    int b = blockIdx.x;
    int tid = threadIdx.x;
    int lane = tid & 31, warp = tid >> 5;

    __shared__ float attb[TBODY];
    __shared__ float attp[TPUN];
    __shared__ float feat[G4];
    __shared__ float sred[8];

    // softmax over rowmax[512]
    float v0 = dec_f(g_rowmax[b * TBODY + tid]);
    float v1 = dec_f(g_rowmax[b * TBODY + 256 + tid]);
    float m = fmaxf(v0, v1);
#pragma unroll
    for (int o = 16; o; o >>= 1) m = fmaxf(m, __shfl_xor_sync(0xFFFFFFFFu, m, o));
    if (lane == 0) sred[warp] = m;
    __syncthreads();
    float M = sred[0];
#pragma unroll
    for (int w = 1; w < 8; w++) M = fmaxf(M, sred[w]);
    __syncthreads();
    float e0 = __expf(v0 - M), e1 = __expf(v1 - M);
    float ss = e0 + e1;
#pragma unroll
    for (int o = 16; o; o >>= 1) ss += __shfl_xor_sync(0xFFFFFFFFu, ss, o);
    if (lane == 0) sred[warp] = ss;
    __syncthreads();
    float S = 0.f;
#pragma unroll
    for (int w = 0; w < 8; w++) S += sred[w];
    __syncthreads();
    attb[tid] = e0 / S;
    attb[256 + tid] = e1 / S;

    // softmax over colmax[256]
    float u = dec_f(g_colmax[b * TPUN + tid]);
    float m2 = u;
#pragma unroll
    for (int o = 16; o; o >>= 1) m2 = fmaxf(m2, __shfl_xor_sync(0xFFFFFFFFu, m2, o));
    if (lane == 0) sred[warp] = m2;
    __syncthreads();
    float M2 = sred[0];
#pragma unroll
    for (int w = 1; w < 8; w++) M2 = fmaxf(M2, sred[w]);
    __syncthreads();
    float e2 = __expf(u - M2);
    float ss2 = e2;
#pragma unroll
    for (int o = 16; o; o >>= 1) ss2 += __shfl_xor_sync(0xFFFFFFFFu, ss2, o);
    if (lane == 0) sred[warp] = ss2;
    __syncthreads();
    float S2 = 0.f;
#pragma unroll
    for (int w = 0; w < 8; w++) S2 += sred[w];
    __syncthreads();
    attp[tid] = e2 / S2;
    __syncthreads();

    // weighted sums -> feat[256]
    if (tid < D2) {
        const float* bm = g_bodyM + (size_t)b * TBODY * D2 + tid;
        float s = 0.f;
#pragma unroll 8
        for (int t = 0; t < TBODY; t++) s += bm[(size_t)t * D2] * attb[t];
        feat[tid] = s;
    } else {
        int d = tid - D2;
        const float* pm = g_punM + (size_t)b * TPUN * D2 + d;
        float s = 0.f;
#pragma unroll 8
        for (int p = 0; p < TPUN; p++) s += pm[(size_t)p * D2] * attp[p];
        feat[D2 + d] = s;
    }
    __syncthreads();

    if (tid < 3) {
        float s = bd[tid];
        for (int k = 0; k < G4; k++) s += feat[k] * Wd[tid * G4 + k];
        outp[b * 3 + tid] = s;
    }
}

// ---------------- host launcher ----------------
extern "C" void kernel_launch(void* const* d_in, const int* in_sizes, int n_in,
                              void* d_out, int out_size)
{
    // Disambiguate input ordering: signature order has bWih_f (76800) at index 3,
    // dict-insertion order has w_u (384) at index 3.
    int base, iwu, iwd, ibd;
    if (in_sizes[3] == 76800) { base = 3; iwu = 15; iwd = 16; ibd = 17; }
    else                      { base = 6; iwu = 3;  iwd = 4;  ibd = 5;  }

    const int*   body_idx = (const int*)d_in[0];
    const int*   pun_idx  = (const int*)d_in[1];
    const float* emb      = (const float*)d_in[2];

    const float* Wih[4]; const float* Whh[4]; const float* bv[4];
    for (int s = 0; s < 4; s++) {
        Wih[s] = (const float*)d_in[base + 3 * s + 0];
        Whh[s] = (const float*)d_in[base + 3 * s + 1];
        bv[s]  = (const float*)d_in[base + 3 * s + 2];
    }
    const float* w_u = (const float*)d_in[iwu];
    const float* Wd  = (const float*)d_in[iwd];
    const float* bd  = (const float*)d_in[ibd];
    float* outp = (float*)d_out;

    zero_kernel<<<256, 256>>>();                              // covers 65536
    mark_kernel<<<(BATCH * (TBODY + TPUN)) / 256, 256>>>(body_idx, pun_idx);

    dim3 gg((VOCAB + BM - 1) / BM, 4, 2);
    gemm_tbl_kernel<<<gg, 256>>>(emb, Wih[0], Wih[1], Wih[2], Wih[3],
                                 bv[0], bv[1], bv[2], bv[3]);

    lstm_kernel<<<512, 256>>>(body_idx, pun_idx, Whh[0], Whh[1], Whh[2], Whh[3]);

    align_kernel<<<BATCH * 8, 256>>>(w_u);

    final_kernel<<<BATCH, 256>>>(Wd, bd, outp);
    (void)n_in; (void)out_size;
}

// round 9
// speedup vs baseline: 1.3817x; 1.0005x over previous
#include <cuda_runtime.h>
#include <cstdint>

#define VOCAB 50000
#define EMBD  300
#define HID   64
#define G4    256      // 4*H
#define D2    128      // 2*H
#define BATCH 128
#define TBODY 512
#define TPUN  256

// ---------------- scratch (static device arrays: allocation-free) ----------------
__device__ float    g_tbl[(size_t)4 * VOCAB * G4];          // 204.8 MB gate tables
__device__ float    g_bodyM[(size_t)BATCH * TBODY * D2];    // 33.5 MB
__device__ float    g_punM[(size_t)BATCH * TPUN * D2];      // 16.8 MB
__device__ unsigned g_rowmax[BATCH * TBODY];                // ordered-int encoded
__device__ unsigned g_colmax[BATCH * TPUN];                 // ordered-int encoded
__device__ int      g_flag[2][VOCAB];                       // 0 body, 1 pun
__device__ int      g_list[2][VOCAB];
__device__ int      g_cnt[2];

// ---------------- helpers ----------------
__device__ __forceinline__ unsigned enc_f(float f) {
    unsigned u = __float_as_uint(f);
    return (u & 0x80000000u) ? ~u : (u | 0x80000000u);
}
__device__ __forceinline__ float dec_f(unsigned u) {
    return __uint_as_float((u & 0x80000000u) ? (u ^ 0x80000000u) : ~u);
}
// packed fp32x2 FMA (sm_100+): 2 FMA per lane per issue
__device__ __forceinline__ unsigned long long ffma2(unsigned long long a,
                                                    unsigned long long b,
                                                    unsigned long long c) {
    unsigned long long d;
    asm("fma.rn.f32x2 %0, %1, %2, %3;" : "=l"(d) : "l"(a), "l"(b), "l"(c));
    return d;
}
__device__ __forceinline__ unsigned long long pk2(float x) {
    unsigned long long r;
    asm("mov.b64 %0, {%1, %1};" : "=l"(r) : "f"(x));
    return r;
}
__device__ __forceinline__ float2 up2(unsigned long long p) {
    float2 r;
    asm("mov.b64 {%0, %1}, %2;" : "=f"(r.x), "=f"(r.y) : "l"(p));
    return r;
}

// ---------------- kernel 0: zero flags/counters + encoded-max arrays ----------------
__global__ void zero_kernel() {
    int i = blockIdx.x * blockDim.x + threadIdx.x;   // grid covers 65536
    if (i < VOCAB) { g_flag[0][i] = 0; g_flag[1][i] = 0; }
    if (i == 0) { g_cnt[0] = 0; g_cnt[1] = 0; }
    if (i < BATCH * TBODY) g_rowmax[i] = 0u;
    if (i < BATCH * TPUN)  g_colmax[i] = 0u;
}

// ---------------- kernel 0b: mark used vocab ids, warp-aggregated compaction ------
__global__ void mark_kernel(const int* __restrict__ body_idx,
                            const int* __restrict__ pun_idx) {
    int i = blockIdx.x * blockDim.x + threadIdx.x;   // 98304 threads
    int which, v;
    if (i < BATCH * TBODY) { which = 0; v = body_idx[i]; }
    else                   { which = 1; v = pun_idx[i - BATCH * TBODY]; }
    // each warp is entirely one type (boundary 65536 is warp-aligned)
    bool isnew = (atomicExch(&g_flag[which][v], 1) == 0);
    unsigned mask = __ballot_sync(0xFFFFFFFFu, isnew);
    int n = __popc(mask);
    if (n) {
        int lane = threadIdx.x & 31;
        int leader = __ffs(mask) - 1;
        int base = 0;
        if (lane == leader) base = atomicAdd(&g_cnt[which], n);
        base = __shfl_sync(0xFFFFFFFFu, base, leader);
        if (isnew) g_list[which][base + __popc(mask & ((1u << lane) - 1))] = v;
    }
}

// ---------------- kernel 1: gate-table GEMM over USED vocab rows ------------------
// grid (391, 4, 2): x = m-block over used list, y = 128-col block of fused N=512
// (y>>1 = direction, y&1 = col half), z = text type (0 body, 1 pun).
// Tile 128x128, BK=20, 256 thr, 8x8 FFMA2 micro, double-buffered smem,
// A-side stored pre-duplicated as f32x2 in smem (no pk2 MOVs in inner loop).
#define BM 128
#define BN 128
#define BK 20
__global__ void __launch_bounds__(256, 2) gemm_tbl_kernel(
    const float* __restrict__ emb,
    const float* __restrict__ W0, const float* __restrict__ W1,
    const float* __restrict__ W2, const float* __restrict__ W3,
    const float* __restrict__ B0, const float* __restrict__ B1,
    const float* __restrict__ B2, const float* __restrict__ B3)
{
    int z = blockIdx.z;
    int cnt = g_cnt[z];
    int m0 = blockIdx.x * BM;
    if (m0 >= cnt) return;
    int y = blockIdx.y;
    int dir = y >> 1;
    int n0 = (y & 1) * 128;          // col offset within this direction's 256
    int seg = z * 2 + dir;
    const float* W    = (seg == 0) ? W0 : (seg == 1) ? W1 : (seg == 2) ? W2 : W3;
    const float* bias = (seg == 0) ? B0 : (seg == 1) ? B1 : (seg == 2) ? B2 : B3;
    float* out = g_tbl + (size_t)seg * VOCAB * G4;

    __shared__ __align__(16) unsigned long long As[2][BK][BM + 2];  // dup f32x2
    __shared__ __align__(16) float Bs[2][BK][BN + 4];
    __shared__ int ids[BM];

    int tid = threadIdx.x;
    int tx = tid & 15, ty = tid >> 4;

    if (tid < BM) ids[tid] = (m0 + tid < cnt) ? g_list[z][m0 + tid] : 0;
    __syncthreads();

    unsigned long long acc[8][4];
#pragma unroll
    for (int i = 0; i < 8; i++)
#pragma unroll
        for (int j = 0; j < 4; j++) acc[i][j] = 0ull;

    float ra[10], rb[10];
#pragma unroll
    for (int it = 0; it < 10; it++) {
        int l = tid + 256 * it;
        int r = l / BK, kk = l - r * BK;
        ra[it] = emb[(size_t)ids[r] * EMBD + kk];
        rb[it] = W[(size_t)(n0 + r) * EMBD + kk];
    }

    for (int ks = 0; ks < 15; ks++) {
        int buf = ks & 1;
#pragma unroll
        for (int it = 0; it < 10; it++) {
            int l = tid + 256 * it;
            int r = l / BK, kk = l - r * BK;
            As[buf][kk][r] = pk2(ra[it]);
            Bs[buf][kk][r] = rb[it];
        }
        __syncthreads();
        if (ks < 14) {
            int k0 = (ks + 1) * BK;
#pragma unroll
            for (int it = 0; it < 10; it++) {
                int l = tid + 256 * it;
                int r = l / BK, kk = l - r * BK;
                ra[it] = emb[(size_t)ids[r] * EMBD + k0 + kk];
                rb[it] = W[(size_t)(n0 + r) * EMBD + k0 + kk];
            }
        }
#pragma unroll
        for (int kk = 0; kk < BK; kk++) {
            ulonglong2 a01 = *(const ulonglong2*)&As[buf][kk][ty * 4];
            ulonglong2 a23 = *(const ulonglong2*)&As[buf][kk][ty * 4 + 2];
            ulonglong2 a45 = *(const ulonglong2*)&As[buf][kk][64 + ty * 4];
            ulonglong2 a67 = *(const ulonglong2*)&As[buf][kk][64 + ty * 4 + 2];
            ulonglong2 b0 = *(const ulonglong2*)&Bs[buf][kk][tx * 4];
            ulonglong2 b1 = *(const ulonglong2*)&Bs[buf][kk][64 + tx * 4];
            unsigned long long ap[8];
            ap[0] = a01.x; ap[1] = a01.y; ap[2] = a23.x; ap[3] = a23.y;
            ap[4] = a45.x; ap[5] = a45.y; ap[6] = a67.x; ap[7] = a67.y;
#pragma unroll
            for (int i = 0; i < 8; i++) {
                acc[i][0] = ffma2(ap[i], b0.x, acc[i][0]);
                acc[i][1] = ffma2(ap[i], b0.y, acc[i][1]);
                acc[i][2] = ffma2(ap[i], b1.x, acc[i][2]);
                acc[i][3] = ffma2(ap[i], b1.y, acc[i][3]);
            }
        }
    }

    float4 bs0 = *(const float4*)&bias[n0 + tx * 4];
    float4 bs1 = *(const float4*)&bias[n0 + 64 + tx * 4];
#pragma unroll
    for (int i = 0; i < 8; i++) {
        int r = ids[ty * 4 + (i & 3) + (i >> 2) * 64];
        float2 v0 = up2(acc[i][0]), v1 = up2(acc[i][1]);
        float2 v2 = up2(acc[i][2]), v3 = up2(acc[i][3]);
        float4 o0 = make_float4(v0.x + bs0.x, v0.y + bs0.y, v1.x + bs0.z, v1.y + bs0.w);
        float4 o1 = make_float4(v2.x + bs1.x, v2.y + bs1.y, v3.x + bs1.z, v3.y + bs1.w);
        *(float4*)&out[(size_t)r * G4 + n0 + tx * 4] = o0;
        *(float4*)&out[(size_t)r * G4 + n0 + 64 + tx * 4] = o1;
    }
}

// ---------------- kernel 2: LSTM, warp-local gate combine -------------------------
// 512 blocks (puns launched first: block seg order XOR 2), 256 thr.
// Warp w owns units 8w..8w+7; lane l computes gate (l>>3) of unit 8w+(l&7).
// Gate combine via 3 shuffles; ONE __syncthreads per step; hs ping-pong buffers.
// Whh row held as 32 packed f32x2 pairs; dot = 32 FFMA2 on broadcast LDS.128.
__global__ void __launch_bounds__(256, 2) lstm_kernel(
    const int* __restrict__ body_idx, const int* __restrict__ pun_idx,
    const float* __restrict__ Whh0, const float* __restrict__ Whh1,
    const float* __restrict__ Whh2, const float* __restrict__ Whh3)
{
    int blk = blockIdx.x;
    int seg = (blk >> 7) ^ 2;        // schedule puns (short) first
    int b   = blk & 127;
    bool isBody = (seg < 2);
    bool isFwd  = ((seg & 1) == 0);
    int T = isBody ? TBODY : TPUN;
    const int* idx = isBody ? (body_idx + b * TBODY) : (pun_idx + b * TPUN);
    const float* Whh = (seg == 0) ? Whh0 : (seg == 1) ? Whh1 : (seg == 2) ? Whh2 : Whh3;
    const float* tbl = g_tbl + (size_t)seg * VOCAB * G4;
    float* out = isBody ? (g_bodyM + (size_t)b * TBODY * D2)
                        : (g_punM  + (size_t)b * TPUN  * D2);
    int off = isFwd ? 0 : HID;

    __shared__ int idx_s[TBODY];
    __shared__ __align__(16) float hs[2][HID];
    __shared__ int len_s;

    int tid  = threadIdx.x;
    int lane = tid & 31;
    int warp = tid >> 5;
    int gc   = lane >> 3;                 // gate class: 0=i,1=f,2=g,3=o
    int u    = (warp << 3) | (lane & 7);  // hidden unit 0..63
    int r    = gc * HID + u;              // gate row 0..255

    if (tid == 0) len_s = 0;
    if (tid < HID) { hs[0][tid] = 0.f; hs[1][tid] = 0.f; }
    __syncthreads();

    int cnt = 0;
    for (int t = tid; t < T; t += 256) {
        int v = idx[t];
        idx_s[t] = v;
        cnt += (v != 0);
    }
#pragma unroll
    for (int o = 16; o; o >>= 1) cnt += __shfl_xor_sync(0xFFFFFFFFu, cnt, o);
    if (lane == 0) atomicAdd(&len_s, cnt);
    __syncthreads();
    int len = len_s;

    // Whh row r as 32 packed f32x2 pairs (row = 256 B, 8B-aligned)
    unsigned long long wp[32];
    {
        const unsigned long long* wr = (const unsigned long long*)(Whh + (size_t)r * HID);
#pragma unroll
        for (int j = 0; j < 32; j++) wp[j] = wr[j];
    }

    float c = 0.f;
    float x1 = 0.f, x2 = 0.f;
    if (len > 0) x1 = tbl[(size_t)idx_s[isFwd ? 0 : (len - 1)] * G4 + r];
    if (len > 1) x2 = tbl[(size_t)idx_s[isFwd ? 1 : (len - 2)] * G4 + r];

    for (int t = 0; t < len; t++) {
        float xs = x1;
        x1 = x2;
        if (t + 2 < len) {
            int p2 = isFwd ? (t + 2) : (len - 3 - t);
            x2 = tbl[(size_t)idx_s[p2] * G4 + r];
        }
        const ulonglong2* hp = (const ulonglong2*)hs[t & 1];
        unsigned long long a0 = 0ull, a1 = 0ull, a2 = 0ull, a3 = 0ull;
#pragma unroll
        for (int jj = 0; jj < 8; jj++) {
            ulonglong2 hA = hp[2 * jj];
            ulonglong2 hB = hp[2 * jj + 1];
            a0 = ffma2(wp[4 * jj + 0], hA.x, a0);
            a1 = ffma2(wp[4 * jj + 1], hA.y, a1);
            a2 = ffma2(wp[4 * jj + 2], hB.x, a2);
            a3 = ffma2(wp[4 * jj + 3], hB.y, a3);
        }
        float2 s0 = up2(a0), s1 = up2(a1), s2 = up2(a2), s3 = up2(a3);
        float pre = xs + ((s0.x + s0.y) + (s1.x + s1.y))
                       + ((s2.x + s2.y) + (s3.x + s3.y));
        float act = (gc == 2) ? tanhf(pre) : 1.f / (1.f + __expf(-pre));
        float fA = __shfl_sync(0xFFFFFFFFu, act, (lane + 8) & 31);
        float gA = __shfl_sync(0xFFFFFFFFu, act, (lane + 16) & 31);
        float oA = __shfl_sync(0xFFFFFFFFu, act, (lane + 24) & 31);
        if (gc == 0) {
            c = fA * c + act * gA;          // act = i-gate
            float h = oA * tanhf(c);
            hs[(t + 1) & 1][u] = h;
            int pos = isFwd ? t : (len - 1 - t);
            out[(size_t)pos * D2 + off + u] = h;
        }
        __syncthreads();
    }
    for (int l = tid; l < (T - len) * HID; l += 256) {
        int tpos = len + l / HID;
        int j = l - (l / HID) * HID;
        out[(size_t)tpos * D2 + off + j] = 0.f;
    }
}

// ---------------- kernel 3: alignment maxes (double-buffered GEMM form) ----------------
// grid = 128 batches * 4 t-chunks * 2 p-chunks = 1024 blocks, 256 thr.
// Tile 128t x 128p, BK=16 over d; body side stored pre-duplicated f32x2 in smem.
#define ABK 16
__global__ void __launch_bounds__(256, 2) align_kernel(const float* __restrict__ w_u)
{
    int bx = blockIdx.x;
    int b  = bx >> 3;
    int tc = (bx >> 1) & 3;
    int pc = bx & 1;
    int t0 = tc * 128;
    int p0 = pc * 128;
    const float* bodyM = g_bodyM + (size_t)b * TBODY * D2;
    const float* punM  = g_punM  + (size_t)b * TPUN  * D2;

    __shared__ __align__(16) unsigned long long Bsu[2][ABK][130];  // [d][t] dup, w3 applied
    __shared__ __align__(16) float Ps[2][ABK][132];                // [d][p]
    __shared__ float a1s[128], a2s[128];
    __shared__ unsigned rms[128], cms[128];

    int tid = threadIdx.x;
    int tx = tid & 15, ty = tid >> 4;
    int warp = tid >> 5, lane = tid & 31;
    int q  = tid & 3;        // d-quad within chunk
    int rr = tid >> 2;       // row 0..63 (+64 on second pass)

    if (tid < 128) { rms[tid] = 0u; cms[tid] = 0u; }
    __syncthreads();

    // a1 (w1·body row) for local 128 t rows; a2 (w2·pun row) for local 128 p rows
    for (int r = warp; r < 128; r += 8) {
        const float* row = bodyM + (size_t)(t0 + r) * D2;
        float s = 0.f;
        for (int d = lane; d < D2; d += 32) s += row[d] * w_u[d];
#pragma unroll
        for (int o = 16; o; o >>= 1) s += __shfl_xor_sync(0xFFFFFFFFu, s, o);
        if (lane == 0) a1s[r] = s;
    }
    for (int r = warp; r < 128; r += 8) {
        const float* row = punM + (size_t)(p0 + r) * D2;
        float s = 0.f;
        for (int d = lane; d < D2; d += 32) s += row[d] * w_u[D2 + d];
#pragma unroll
        for (int o = 16; o; o >>= 1) s += __shfl_xor_sync(0xFFFFFFFFu, s, o);
        if (lane == 0) a2s[r] = s;
    }

    unsigned long long acc[8][4];
#pragma unroll
    for (int i = 0; i < 8; i++)
#pragma unroll
        for (int j = 0; j < 4; j++) acc[i][j] = 0ull;

    // prefetch chunk 0
    float4 bv[2], pv[2];
    {
        float4 w3v = *(const float4*)&w_u[2 * D2 + 4 * q];
#pragma unroll
        for (int i = 0; i < 2; i++) {
            int r = rr + 64 * i;
            float4 v = *(const float4*)&bodyM[(size_t)(t0 + r) * D2 + 4 * q];
            bv[i] = make_float4(v.x * w3v.x, v.y * w3v.y, v.z * w3v.z, v.w * w3v.w);
            pv[i] = *(const float4*)&punM[(size_t)(p0 + r) * D2 + 4 * q];
        }
    }

    for (int kc = 0; kc < 8; kc++) {
        int buf = kc & 1;
#pragma unroll
        for (int i = 0; i < 2; i++) {
            int r = rr + 64 * i;
            Bsu[buf][4 * q + 0][r] = pk2(bv[i].x);
            Bsu[buf][4 * q + 1][r] = pk2(bv[i].y);
            Bsu[buf][4 * q + 2][r] = pk2(bv[i].z);
            Bsu[buf][4 * q + 3][r] = pk2(bv[i].w);
            Ps[buf][4 * q + 0][r] = pv[i].x;
            Ps[buf][4 * q + 1][r] = pv[i].y;
            Ps[buf][4 * q + 2][r] = pv[i].z;
            Ps[buf][4 * q + 3][r] = pv[i].w;
        }
        __syncthreads();
        if (kc < 7) {
            int d0 = (kc + 1) * ABK;
            float4 w3v = *(const float4*)&w_u[2 * D2 + d0 + 4 * q];
#pragma unroll
            for (int i = 0; i < 2; i++) {
                int r = rr + 64 * i;
                float4 v = *(const float4*)&bodyM[(size_t)(t0 + r) * D2 + d0 + 4 * q];
                bv[i] = make_float4(v.x * w3v.x, v.y * w3v.y, v.z * w3v.z, v.w * w3v.w);
                pv[i] = *(const float4*)&punM[(size_t)(p0 + r) * D2 + d0 + 4 * q];
            }
        }
#pragma unroll
        for (int d = 0; d < ABK; d++) {
            ulonglong2 a01 = *(const ulonglong2*)&Bsu[buf][d][ty * 4];
            ulonglong2 a23 = *(const ulonglong2*)&Bsu[buf][d][ty * 4 + 2];
            ulonglong2 a45 = *(const ulonglong2*)&Bsu[buf][d][64 + ty * 4];
            ulonglong2 a67 = *(const ulonglong2*)&Bsu[buf][d][64 + ty * 4 + 2];
            ulonglong2 b0 = *(const ulonglong2*)&Ps[buf][d][tx * 4];
            ulonglong2 b1 = *(const ulonglong2*)&Ps[buf][d][64 + tx * 4];
            unsigned long long ap[8];
            ap[0] = a01.x; ap[1] = a01.y; ap[2] = a23.x; ap[3] = a23.y;
            ap[4] = a45.x; ap[5] = a45.y; ap[6] = a67.x; ap[7] = a67.y;
#pragma unroll
            for (int i = 0; i < 8; i++) {
                acc[i][0] = ffma2(ap[i], b0.x, acc[i][0]);
                acc[i][1] = ffma2(ap[i], b0.y, acc[i][1]);
                acc[i][2] = ffma2(ap[i], b1.x, acc[i][2]);
                acc[i][3] = ffma2(ap[i], b1.y, acc[i][3]);
            }
        }
    }

    // combine with a1/a2, reduce maxes
    float rmax[8], cmax[8];
#pragma unroll
    for (int i = 0; i < 8; i++) { rmax[i] = -1e30f; cmax[i] = -1e30f; }
#pragma unroll
    for (int i = 0; i < 8; i++) {
        int trow = ty * 4 + (i & 3) + (i >> 2) * 64;
        float a1v = a1s[trow];
#pragma unroll
        for (int jp = 0; jp < 4; jp++) {
            float2 v = up2(acc[i][jp]);
            int c0 = tx * 4 + (jp >> 1) * 64 + (jp & 1) * 2;
            float v0 = v.x + a1v + a2s[c0];
            float v1 = v.y + a1v + a2s[c0 + 1];
            rmax[i] = fmaxf(rmax[i], fmaxf(v0, v1));
            int jj = (jp >> 1) * 4 + (jp & 1) * 2;
            cmax[jj]     = fmaxf(cmax[jj], v0);
            cmax[jj + 1] = fmaxf(cmax[jj + 1], v1);
        }
    }
#pragma unroll
    for (int i = 0; i < 8; i++) {
        int trow = ty * 4 + (i & 3) + (i >> 2) * 64;
        atomicMax(&rms[trow], enc_f(rmax[i]));
    }
#pragma unroll
    for (int j = 0; j < 8; j++) {
        int col = tx * 4 + (j >> 2) * 64 + (j & 3);
        atomicMax(&cms[col], enc_f(cmax[j]));
    }
    __syncthreads();

    if (tid < 128) {
        atomicMax(&g_rowmax[b * TBODY + t0 + tid], rms[tid]);
        atomicMax(&g_colmax[b * TPUN + p0 + tid], cms[tid]);
    }
}

// ---------------- kernel 4: softmaxes + weighted sums + final linear ----------------
__global__ void __launch_bounds__(256) final_kernel(
    const float* __restrict__ Wd, const float* __restrict__ bd,
    float* __restrict__ outp)
{
    int b = blockIdx.x;
    int tid = threadIdx.x;
    int lane = tid & 31, warp = tid >> 5;

    __shared__ float attb[TBODY];
    __shared__ float attp[TPUN];
    __shared__ float feat[G4];
    __shared__ float sred[8];

    // softmax over rowmax[512]
    float v0 = dec_f(g_rowmax[b * TBODY + tid]);
    float v1 = dec_f(g_rowmax[b * TBODY + 256 + tid]);
    float m = fmaxf(v0, v1);
#pragma unroll
    for (int o = 16; o; o >>= 1) m = fmaxf(m, __shfl_xor_sync(0xFFFFFFFFu, m, o));
    if (lane == 0) sred[warp] = m;
    __syncthreads();
    float M = sred[0];
#pragma unroll
    for (int w = 1; w < 8; w++) M = fmaxf(M, sred[w]);
    __syncthreads();
    float e0 = __expf(v0 - M), e1 = __expf(v1 - M);
    float ss = e0 + e1;
#pragma unroll
    for (int o = 16; o; o >>= 1) ss += __shfl_xor_sync(0xFFFFFFFFu, ss, o);
    if (lane == 0) sred[warp] = ss;
    __syncthreads();
    float S = 0.f;
#pragma unroll
    for (int w = 0; w < 8; w++) S += sred[w];
    __syncthreads();
    attb[tid] = e0 / S;
    attb[256 + tid] = e1 / S;

    // softmax over colmax[256]
    float u = dec_f(g_colmax[b * TPUN + tid]);
    float m2 = u;
#pragma unroll
    for (int o = 16; o; o >>= 1) m2 = fmaxf(m2, __shfl_xor_sync(0xFFFFFFFFu, m2, o));
    if (lane == 0) sred[warp] = m2;
    __syncthreads();
    float M2 = sred[0];
#pragma unroll
    for (int w = 1; w < 8; w++) M2 = fmaxf(M2, sred[w]);
    __syncthreads();
    float e2 = __expf(u - M2);
    float ss2 = e2;
#pragma unroll
    for (int o = 16; o; o >>= 1) ss2 += __shfl_xor_sync(0xFFFFFFFFu, ss2, o);
    if (lane == 0) sred[warp] = ss2;
    __syncthreads();
    float S2 = 0.f;
#pragma unroll
    for (int w = 0; w < 8; w++) S2 += sred[w];
    __syncthreads();
    attp[tid] = e2 / S2;
    __syncthreads();

    // weighted sums -> feat[256]
    if (tid < D2) {
        const float* bm = g_bodyM + (size_t)b * TBODY * D2 + tid;
        float s = 0.f;
#pragma unroll 8
        for (int t = 0; t < TBODY; t++) s += bm[(size_t)t * D2] * attb[t];
        feat[tid] = s;
    } else {
        int d = tid - D2;
        const float* pm = g_punM + (size_t)b * TPUN * D2 + d;
        float s = 0.f;
#pragma unroll 8
        for (int p = 0; p < TPUN; p++) s += pm[(size_t)p * D2] * attp[p];
        feat[D2 + d] = s;
    }
    __syncthreads();

    if (tid < 3) {
        float s = bd[tid];
        for (int k = 0; k < G4; k++) s += feat[k] * Wd[tid * G4 + k];
        outp[b * 3 + tid] = s;
    }
}

// ---------------- host launcher ----------------
extern "C" void kernel_launch(void* const* d_in, const int* in_sizes, int n_in,
                              void* d_out, int out_size)
{
    // Disambiguate input ordering: signature order has bWih_f (76800) at index 3,
    // dict-insertion order has w_u (384) at index 3.
    int base, iwu, iwd, ibd;
    if (in_sizes[3] == 76800) { base = 3; iwu = 15; iwd = 16; ibd = 17; }
    else                      { base = 6; iwu = 3;  iwd = 4;  ibd = 5;  }

    const int*   body_idx = (const int*)d_in[0];
    const int*   pun_idx  = (const int*)d_in[1];
    const float* emb      = (const float*)d_in[2];

    const float* Wih[4]; const float* Whh[4]; const float* bv[4];
    for (int s = 0; s < 4; s++) {
        Wih[s] = (const float*)d_in[base + 3 * s + 0];
        Whh[s] = (const float*)d_in[base + 3 * s + 1];
        bv[s]  = (const float*)d_in[base + 3 * s + 2];
    }
    const float* w_u = (const float*)d_in[iwu];
    const float* Wd  = (const float*)d_in[iwd];
    const float* bd  = (const float*)d_in[ibd];
    float* outp = (float*)d_out;

    zero_kernel<<<256, 256>>>();                              // covers 65536
    mark_kernel<<<(BATCH * (TBODY + TPUN)) / 256, 256>>>(body_idx, pun_idx);

    dim3 gg((VOCAB + BM - 1) / BM, 4, 2);
    gemm_tbl_kernel<<<gg, 256>>>(emb, Wih[0], Wih[1], Wih[2], Wih[3],
                                 bv[0], bv[1], bv[2], bv[3]);

    lstm_kernel<<<512, 256>>>(body_idx, pun_idx, Whh[0], Whh[1], Whh[2], Whh[3]);

    align_kernel<<<BATCH * 8, 256>>>(w_u);

    final_kernel<<<BATCH, 256>>>(Wd, bd, outp);
    (void)n_in; (void)out_size;
}